// round 2
// baseline (speedup 1.0000x reference)
#include <cuda_runtime.h>
#include <math.h>

#define Bdim 64
#define Tdim 1024
#define Idim 512
#define Hdim 512
#define N2H  1024

// ---- device scratch (static: no allocations allowed) ----
__device__ float g_z[Bdim * Tdim * Hdim];      // z = sigmoid(xW+b), [B][T][H], 128MB
__device__ float g_y[2 * 8 * Hdim * 8];        // double-buffered y: [buf][group][k=512][b=8]
__device__ unsigned g_cnt[8];                  // per-group monotonic barrier counters

// ---------- acquire/release helpers ----------
__device__ __forceinline__ unsigned ld_acq(const unsigned* p) {
    unsigned v;
    asm volatile("ld.acquire.gpu.global.u32 %0, [%1];" : "=r"(v) : "l"(p) : "memory");
    return v;
}
__device__ __forceinline__ void red_rel_add(unsigned* p, unsigned v) {
    asm volatile("red.release.gpu.global.add.u32 [%0], %1;" :: "l"(p), "r"(v) : "memory");
}

__device__ __forceinline__ void group_barrier(unsigned* cnt, unsigned target) {
    __syncthreads();
    if (threadIdx.x == 0) {
        red_rel_add(cnt, 1u);
        unsigned it = 0;
        while (ld_acq(cnt) < target) {
            if (++it > 400000000u) break;   // safety: never hang the container
        }
    }
    __syncthreads();
}

// =====================================================================
// Phase 1: z[b][t][h] = sigmoid( sum_i x[b][t][i] * W[i][h] + bw[h] )
// Classic 128x128x16 fp32 SGEMM, 256 threads, 8x8 register tiles.
// Also resets the phase-2 barrier counters (runs before phase 2 in-stream).
// =====================================================================
#define BM 128
#define BN 128
#define BK 16
#define AST 132   // padded As row stride

__global__ __launch_bounds__(256) void phase1(const float* __restrict__ x,
                                              const float* __restrict__ W,
                                              const float* __restrict__ bw) {
    if (blockIdx.x == 0 && blockIdx.y == 0 && threadIdx.x < 8)
        g_cnt[threadIdx.x] = 0;

    __shared__ float As[BK * AST];   // transposed: As[k][m]
    __shared__ float Bs[BK * BN];    // Bs[k][n]

    const int tid = threadIdx.x;
    const int bn0 = blockIdx.x * BN;
    const int bm0 = blockIdx.y * BM;
    const int tm  = (tid >> 4) << 3;   // 0..120
    const int tn  = (tid & 15) << 3;   // 0..120

    float acc[8][8];
#pragma unroll
    for (int i = 0; i < 8; ++i)
#pragma unroll
        for (int j = 0; j < 8; ++j) acc[i][j] = 0.f;

    const int arow = tid >> 2;          // 0..63
    const int acol = (tid & 3) << 2;    // 0,4,8,12
    const int brow = tid >> 5;          // 0..7
    const int bcol = (tid & 31) << 2;   // 0..124

    for (int k0 = 0; k0 < Idim; k0 += BK) {
        float4 a0 = *(const float4*)&x[(size_t)(bm0 + arow)      * Idim + k0 + acol];
        float4 a1 = *(const float4*)&x[(size_t)(bm0 + arow + 64) * Idim + k0 + acol];
        float4 b0 = *(const float4*)&W[(size_t)(k0 + brow)     * Hdim + bn0 + bcol];
        float4 b1 = *(const float4*)&W[(size_t)(k0 + brow + 8) * Hdim + bn0 + bcol];
        __syncthreads();
        As[(acol + 0) * AST + arow] = a0.x;
        As[(acol + 1) * AST + arow] = a0.y;
        As[(acol + 2) * AST + arow] = a0.z;
        As[(acol + 3) * AST + arow] = a0.w;
        As[(acol + 0) * AST + arow + 64] = a1.x;
        As[(acol + 1) * AST + arow + 64] = a1.y;
        As[(acol + 2) * AST + arow + 64] = a1.z;
        As[(acol + 3) * AST + arow + 64] = a1.w;
        *(float4*)&Bs[brow * BN + bcol]       = b0;
        *(float4*)&Bs[(brow + 8) * BN + bcol] = b1;
        __syncthreads();
#pragma unroll
        for (int k = 0; k < BK; ++k) {
            float4 ra0 = *(const float4*)&As[k * AST + tm];
            float4 ra1 = *(const float4*)&As[k * AST + tm + 4];
            float4 rb0 = *(const float4*)&Bs[k * BN + tn];
            float4 rb1 = *(const float4*)&Bs[k * BN + tn + 4];
            float av[8] = {ra0.x, ra0.y, ra0.z, ra0.w, ra1.x, ra1.y, ra1.z, ra1.w};
            float bv[8] = {rb0.x, rb0.y, rb0.z, rb0.w, rb1.x, rb1.y, rb1.z, rb1.w};
#pragma unroll
            for (int i = 0; i < 8; ++i)
#pragma unroll
                for (int j = 0; j < 8; ++j) acc[i][j] += av[i] * bv[j];
        }
    }

    // epilogue: bias + sigmoid, store to g_z[m*512 + n]
    float bias[8];
#pragma unroll
    for (int j = 0; j < 8; ++j) bias[j] = bw[bn0 + tn + j];
#pragma unroll
    for (int i = 0; i < 8; ++i) {
        const size_t mg = (size_t)(bm0 + tm + i);
        float v[8];
#pragma unroll
        for (int j = 0; j < 8; ++j) {
            float p = acc[i][j] + bias[j];
            v[j] = 1.f / (1.f + __expf(-p));
        }
        *(float4*)&g_z[mg * Hdim + bn0 + tn]     = make_float4(v[0], v[1], v[2], v[3]);
        *(float4*)&g_z[mg * Hdim + bn0 + tn + 4] = make_float4(v[4], v[5], v[6], v[7]);
    }
}

// =====================================================================
// Phase 2: persistent recurrence. 128 CTAs = 8 groups x 16 CTAs.
// Group g owns batch rows [8g, 8g+8). CTA c in group owns h in [32c, 32c+32)
// i.e. R columns {32c..32c+31} (i) and {512+32c..512+32c+31} (o),
// held resident in smem (128KB). Per step: mini-GEMM 8b x 64n x 512k with
// 8x8 register tiles and k-split 32, warp-shfl + smem reduction, epilogue,
// 16-CTA group barrier via monotonic release/acquire counter.
// =====================================================================
__global__ __launch_bounds__(256) void phase2(const float* __restrict__ Rm,
                                              const float* __restrict__ br,
                                              const float* __restrict__ y0,
                                              const float* __restrict__ c0,
                                              float* __restrict__ out,
                                              int tail) {
    extern __shared__ float sm[];
    float* R_s  = sm;               // 512*64 = 32768 floats
    float* y_s  = sm + 32768;       // 512*8  = 4096
    float* red  = sm + 36864;       // 8 warps * 8 g * 68 = 4352 (padded)
    float* rsum = sm + 41216;       // 512
    float* c_s  = sm + 41728;       // 256
    float* bias = sm + 41984;       // 64
    // total 42048 floats = 168192 bytes

    const int tid   = threadIdx.x;
    const int g     = blockIdx.x >> 4;     // group 0..7
    const int cta   = blockIdx.x & 15;     // 0..15
    const int hbase = cta * 32;

    // ---- one-time: load resident R slice (K-major rows, 64 cols) ----
    for (int idx = tid; idx < 512 * 64; idx += 256) {
        const int k = idx >> 6, j = idx & 63;
        const int col = (j < 32) ? (hbase + j) : (480 + hbase + j);  // 512+hbase+(j-32)
        R_s[idx] = Rm[(size_t)k * N2H + col];
    }
    if (tid < 64) {
        const int col = (tid < 32) ? (hbase + tid) : (480 + hbase + tid);
        bias[tid] = br[col];
    }
    {   // init c and prefill y buffer 0 with y0 (layout [g][k=h][b])
        const int b = tid >> 5, h = tid & 31;
        c_s[tid] = c0[(g * 8 + b) * Hdim + hbase + h];
        g_y[g * 4096 + (hbase + h) * 8 + b] = y0[(g * 8 + b) * Hdim + hbase + h];
    }
    unsigned target = 16;
    group_barrier(&g_cnt[g], target); target += 16;

    const int gg = tid & 7;        // n-group (8 cols)
    const int kc = tid >> 3;       // k-split 0..31, chunk of 16
    const float* rsp = R_s + (kc << 10) + (gg << 3);   // kc*16*64 + gg*8
    const float* ysp = y_s + (kc << 7);                // kc*16*8
    const int w = tid >> 5;
    const int q = (tid >> 3) & 3;

    for (int t = 0; t < Tdim; ++t) {
        // ---- load group's y (double-buffered, L2-only reads) ----
        {
            const int p = t & 1;
            const float4* src = (const float4*)(g_y + p * 32768 + g * 4096);
            float4* dst = (float4*)y_s;
#pragma unroll
            for (int i = 0; i < 4; ++i)
                dst[tid + i * 256] = __ldcg(src + tid + i * 256);
        }
        __syncthreads();

        // ---- mini-GEMM: acc[b][n] = sum over 16 k of y[b][k]*R[k][n] ----
        float acc[8][8];
#pragma unroll
        for (int i = 0; i < 8; ++i)
#pragma unroll
            for (int j = 0; j < 8; ++j) acc[i][j] = 0.f;
#pragma unroll
        for (int k = 0; k < 16; ++k) {
            float4 ya = *(const float4*)(ysp + k * 8);
            float4 yb = *(const float4*)(ysp + k * 8 + 4);
            float4 ra = *(const float4*)(rsp + k * 64);
            float4 rb = *(const float4*)(rsp + k * 64 + 4);
            float yv[8] = {ya.x, ya.y, ya.z, ya.w, yb.x, yb.y, yb.z, yb.w};
            float rv[8] = {ra.x, ra.y, ra.z, ra.w, rb.x, rb.y, rb.z, rb.w};
#pragma unroll
            for (int bb = 0; bb < 8; ++bb)
#pragma unroll
                for (int nn = 0; nn < 8; ++nn) acc[bb][nn] += yv[bb] * rv[nn];
        }

        // ---- reduce k-splits: bfly over the 4 kc's inside each warp ----
#pragma unroll
        for (int bb = 0; bb < 8; ++bb)
#pragma unroll
            for (int nn = 0; nn < 8; ++nn) {
                acc[bb][nn] += __shfl_xor_sync(0xffffffffu, acc[bb][nn], 8);
                acc[bb][nn] += __shfl_xor_sync(0xffffffffu, acc[bb][nn], 16);
            }
        // each quarter of the warp writes 2 of the 8 b-rows (all hold warp sum)
        {
            float* rp = red + w * 544 + gg * 68;
#pragma unroll
            for (int bb2 = 0; bb2 < 2; ++bb2) {
                const int bb = 2 * q + bb2;
                *(float4*)(rp + bb * 8)     = make_float4(acc[bb][0], acc[bb][1], acc[bb][2], acc[bb][3]);
                *(float4*)(rp + bb * 8 + 4) = make_float4(acc[bb][4], acc[bb][5], acc[bb][6], acc[bb][7]);
            }
        }
        __syncthreads();

        // ---- cross-warp reduce -> rsum[b*64 + n] ----
        for (int o = tid; o < 512; o += 256) {
            const int b = o >> 6, n6 = o & 63, gi = n6 >> 3, ni = n6 & 7;
            float s = 0.f;
#pragma unroll
            for (int ww = 0; ww < 8; ++ww) s += red[ww * 544 + gi * 68 + b * 8 + ni];
            rsum[o] = s;
        }
        __syncthreads();

        // ---- epilogue: activations, state update, outputs ----
        {
            const int b = tid >> 5, h = tid & 31;
            const float iv = tanhf(rsum[b * 64 + h]      + bias[h]);
            const float ov = tanhf(rsum[b * 64 + 32 + h] + bias[32 + h]);
            const float z  = g_z[((size_t)(g * 8 + b) * Tdim + t) * Hdim + hbase + h];
            const float c  = c_s[tid] + iv * z;
            c_s[tid] = c;
            const float y = ov * tanhf(c);
            out[((size_t)t * Bdim + (g * 8 + b)) * Hdim + hbase + h] = y;
            const int np = (t + 1) & 1;
            g_y[np * 32768 + g * 4096 + (hbase + h) * 8 + b] = y;
            if (tail && t == Tdim - 1) {
                const size_t base = (size_t)Tdim * Bdim * Hdim;
                out[base + (size_t)(g * 8 + b) * Hdim + hbase + h] = y;               // y_f
                out[base + (size_t)Bdim * Hdim + (size_t)(g * 8 + b) * Hdim + hbase + h] = c;  // c_f
            }
        }

        if (t < Tdim - 1) {
            group_barrier(&g_cnt[g], target);
            target += 16;
        }
    }
}

// =====================================================================
extern "C" void kernel_launch(void* const* d_in, const int* in_sizes, int n_in,
                              void* d_out, int out_size) {
    const float* x  = (const float*)d_in[0];
    const float* W  = (const float*)d_in[1];
    const float* R  = (const float*)d_in[2];
    const float* br = (const float*)d_in[3];
    const float* bw = (const float*)d_in[4];
    const float* y0 = (const float*)d_in[5];
    const float* c0 = (const float*)d_in[6];
    float* out = (float*)d_out;

    const int smem2 = 42048 * 4;  // 168192 bytes
    cudaFuncSetAttribute(phase2, cudaFuncAttributeMaxDynamicSharedMemorySize, smem2);

    dim3 g1(Hdim / BN, (Bdim * Tdim) / BM);   // (4, 512)
    phase1<<<g1, 256>>>(x, W, bw);

    const long long full = (long long)Tdim * Bdim * Hdim + 2LL * Bdim * Hdim;
    const int tail = ((long long)out_size >= full) ? 1 : 0;
    phase2<<<128, 256, smem2>>>(R, br, y0, c0, out, tail);
}

// round 5
// speedup vs baseline: 1.4426x; 1.4426x over previous
#include <cuda_runtime.h>
#include <cuda_fp16.h>
#include <math.h>
#include <stdint.h>

#define Bdim 64
#define Tdim 1024
#define Idim 512
#define Hdim 512
#define N2H  1024

// ---- device scratch (static: no allocations allowed) ----
__device__ float g_z[Bdim * Tdim * Hdim];                       // z = sigmoid(xW+b), [B*T][H]
__device__ __align__(16) unsigned short g_yhi[2 * Bdim * Hdim]; // y hi fp16, [buf][b][h]
__device__ __align__(16) unsigned short g_ylo[2 * Bdim * Hdim]; // y lo fp16
__device__ unsigned g_cnt[8];                                    // per-group barrier counters

// ---------- acquire/release helpers ----------
__device__ __forceinline__ unsigned ld_acq(const unsigned* p) {
    unsigned v;
    asm volatile("ld.acquire.gpu.global.u32 %0, [%1];" : "=r"(v) : "l"(p) : "memory");
    return v;
}
__device__ __forceinline__ void red_rel_add(unsigned* p, unsigned v) {
    asm volatile("red.release.gpu.global.add.u32 [%0], %1;" :: "l"(p), "r"(v) : "memory");
}
__device__ __forceinline__ void group_barrier(unsigned* cnt, unsigned target) {
    __syncthreads();
    if (threadIdx.x == 0) {
        red_rel_add(cnt, 1u);
        unsigned it = 0;
        while (ld_acq(cnt) < target) {
            if (++it > 400000000u) break;   // safety: never hang
        }
    }
    __syncthreads();
}

__device__ __forceinline__ uint32_t smem_u32(const void* p) {
    uint32_t a;
    asm("{ .reg .u64 t; cvta.to.shared.u64 t, %1; cvt.u32.u64 %0, t; }" : "=r"(a) : "l"(p));
    return a;
}
__device__ __forceinline__ float tanh_fast(float x) {
    float e = __expf(2.f * x);
    return 1.f - 2.f / (e + 1.f);
}
__device__ __forceinline__ uint32_t packh2(__half a, __half b) {
    __half2 h = __halves2half2(a, b);
    return *(uint32_t*)&h;
}

#define LDSM_X4(r0, r1, r2, r3, addr) \
    asm volatile("ldmatrix.sync.aligned.m8n8.x4.shared.b16 {%0,%1,%2,%3}, [%4];" \
        : "=r"(r0), "=r"(r1), "=r"(r2), "=r"(r3) : "r"(addr))

#define MMA16816(d, a0, a1, a2, a3, b0, b1) \
    asm volatile("mma.sync.aligned.m16n8k16.row.col.f32.f16.f16.f32 " \
        "{%0,%1,%2,%3}, {%4,%5,%6,%7}, {%8,%9}, {%0,%1,%2,%3};" \
        : "+f"((d)[0]), "+f"((d)[1]), "+f"((d)[2]), "+f"((d)[3]) \
        : "r"(a0), "r"(a1), "r"(a2), "r"(a3), "r"(b0), "r"(b1))

// =====================================================================
// Phase 1: z = sigmoid(x @ W + bw).  FFMA SGEMM 128x128x16 (known-good).
// Also resets the phase-2 barrier counters.
// =====================================================================
#define BM 128
#define BN 128
#define BK 16
#define AST 132

__global__ __launch_bounds__(256) void phase1(const float* __restrict__ x,
                                              const float* __restrict__ W,
                                              const float* __restrict__ bw) {
    if (blockIdx.x == 0 && blockIdx.y == 0 && threadIdx.x < 8)
        g_cnt[threadIdx.x] = 0;

    __shared__ float As[BK * AST];
    __shared__ float Bs[BK * BN];

    const int tid = threadIdx.x;
    const int bn0 = blockIdx.x * BN;
    const int bm0 = blockIdx.y * BM;
    const int tm  = (tid >> 4) << 3;
    const int tn  = (tid & 15) << 3;

    float acc[8][8];
#pragma unroll
    for (int i = 0; i < 8; ++i)
#pragma unroll
        for (int j = 0; j < 8; ++j) acc[i][j] = 0.f;

    const int arow = tid >> 2;
    const int acol = (tid & 3) << 2;
    const int brow = tid >> 5;
    const int bcol = (tid & 31) << 2;

    for (int k0 = 0; k0 < Idim; k0 += BK) {
        float4 a0 = *(const float4*)&x[(size_t)(bm0 + arow)      * Idim + k0 + acol];
        float4 a1 = *(const float4*)&x[(size_t)(bm0 + arow + 64) * Idim + k0 + acol];
        float4 b0 = *(const float4*)&W[(size_t)(k0 + brow)     * Hdim + bn0 + bcol];
        float4 b1 = *(const float4*)&W[(size_t)(k0 + brow + 8) * Hdim + bn0 + bcol];
        __syncthreads();
        As[(acol + 0) * AST + arow] = a0.x;
        As[(acol + 1) * AST + arow] = a0.y;
        As[(acol + 2) * AST + arow] = a0.z;
        As[(acol + 3) * AST + arow] = a0.w;
        As[(acol + 0) * AST + arow + 64] = a1.x;
        As[(acol + 1) * AST + arow + 64] = a1.y;
        As[(acol + 2) * AST + arow + 64] = a1.z;
        As[(acol + 3) * AST + arow + 64] = a1.w;
        *(float4*)&Bs[brow * BN + bcol]       = b0;
        *(float4*)&Bs[(brow + 8) * BN + bcol] = b1;
        __syncthreads();
#pragma unroll
        for (int k = 0; k < BK; ++k) {
            float4 ra0 = *(const float4*)&As[k * AST + tm];
            float4 ra1 = *(const float4*)&As[k * AST + tm + 4];
            float4 rb0 = *(const float4*)&Bs[k * BN + tn];
            float4 rb1 = *(const float4*)&Bs[k * BN + tn + 4];
            float av[8] = {ra0.x, ra0.y, ra0.z, ra0.w, ra1.x, ra1.y, ra1.z, ra1.w};
            float bv[8] = {rb0.x, rb0.y, rb0.z, rb0.w, rb1.x, rb1.y, rb1.z, rb1.w};
#pragma unroll
            for (int i = 0; i < 8; ++i)
#pragma unroll
                for (int j = 0; j < 8; ++j) acc[i][j] += av[i] * bv[j];
        }
    }

    float bias[8];
#pragma unroll
    for (int j = 0; j < 8; ++j) bias[j] = bw[bn0 + tn + j];
#pragma unroll
    for (int i = 0; i < 8; ++i) {
        const size_t mg = (size_t)(bm0 + tm + i);
        float v[8];
#pragma unroll
        for (int j = 0; j < 8; ++j) {
            float p = acc[i][j] + bias[j];
            v[j] = 1.f / (1.f + __expf(-p));
        }
        *(float4*)&g_z[mg * Hdim + bn0 + tn]     = make_float4(v[0], v[1], v[2], v[3]);
        *(float4*)&g_z[mg * Hdim + bn0 + tn + 4] = make_float4(v[4], v[5], v[6], v[7]);
    }
}

// =====================================================================
// Phase 2: HMMA recurrence.  128 CTAs = 4 groups x 32 CTAs.
// Group g owns batches [16g, 16g+16) (M=16, no mma padding).
// CTA c owns output h in [16c, 16c+16): R cols 16c..16c+15 (i) and
// 512+16c..+15 (o) = 4 n-tiles of 8.  K=512.
// 8 warps = 4 n-tiles x 2 K-halves; B fragments (R hi/lo fp16) resident
// in registers.  A = group's y (hi/lo fp16) reloaded each step from a
// double-buffered global into swizzled smem; 3-term split mma
// (hi*hi + lo*hi + hi*lo) gives ~fp32 accuracy.  One 32-CTA
// release/acquire barrier per step.
// =====================================================================
__global__ __launch_bounds__(256, 1) void phase2(const float* __restrict__ Rm,
                                                 const float* __restrict__ br,
                                                 const float* __restrict__ y0,
                                                 const float* __restrict__ c0,
                                                 float* __restrict__ out,
                                                 int tail) {
    __shared__ __align__(16) unsigned char sAhi[16 * 1024];   // 16 rows x 512 fp16
    __shared__ __align__(16) unsigned char sAlo[16 * 1024];
    __shared__ float4 red4[8 * 32];                            // [warp][lane]

    const int tid  = threadIdx.x;
    const int w    = tid >> 5;
    const int lane = tid & 31;
    const int g    = blockIdx.x >> 5;     // 0..3
    const int c    = blockIdx.x & 31;     // 0..31
    const int cbase = c * 16;
    const int nw = w & 3;                 // n-tile
    const int kh = w >> 2;                // K half
    const int tig = lane & 3;
    const int gid = lane >> 2;

    // ---- resident B fragments: R slice, fp16 hi/lo ----
    uint32_t bh[16][2], bl[16][2];
    {
        const int nCol = (nw < 2) ? (cbase + nw * 8 + gid)
                                  : (512 + cbase + (nw - 2) * 8 + gid);
#pragma unroll
        for (int kt = 0; kt < 16; ++kt) {
            const int k0 = (kh * 16 + kt) * 16 + tig * 2;
            float v0 = Rm[(size_t)(k0)     * N2H + nCol];
            float v1 = Rm[(size_t)(k0 + 1) * N2H + nCol];
            float v2 = Rm[(size_t)(k0 + 8) * N2H + nCol];
            float v3 = Rm[(size_t)(k0 + 9) * N2H + nCol];
            __half h0 = __float2half_rn(v0), h1 = __float2half_rn(v1);
            __half h2 = __float2half_rn(v2), h3 = __float2half_rn(v3);
            bh[kt][0] = packh2(h0, h1);
            bh[kt][1] = packh2(h2, h3);
            bl[kt][0] = packh2(__float2half_rn(v0 - __half2float(h0)),
                               __float2half_rn(v1 - __half2float(h1)));
            bl[kt][1] = packh2(__float2half_rn(v2 - __half2float(h2)),
                               __float2half_rn(v3 - __half2float(h3)));
        }
    }

    // ---- ldmatrix lane addressing (row + swizzle xor precomputed) ----
    const int q  = lane >> 3;
    const int lr = lane & 7;
    const int rowA = lr + (q & 1) * 8;
    const int cq   = q >> 1;
    const uint32_t aHiBase = smem_u32(sAhi) + (uint32_t)rowA * 1024u;
    const uint32_t aLoBase = smem_u32(sAlo) + (uint32_t)rowA * 1024u;

    // ---- epilogue state (warps 0,1): bias, c registers ----
    const int h0  = cbase + nw * 8 + tig * 2;   // valid for w<2 (nw==w)
    const int gbA = g * 16 + gid;
    const int gbB = gbA + 8;
    float bi0 = 0, bi1 = 0, bo0 = 0, bo1 = 0;
    float cA0 = 0, cA1 = 0, cB0 = 0, cB1 = 0;
    if (w < 2) {
        bi0 = br[h0];       bi1 = br[h0 + 1];
        bo0 = br[512 + h0]; bo1 = br[512 + h0 + 1];
        cA0 = c0[(size_t)gbA * Hdim + h0];
        cA1 = c0[(size_t)gbA * Hdim + h0 + 1];
        cB0 = c0[(size_t)gbB * Hdim + h0];
        cB1 = c0[(size_t)gbB * Hdim + h0 + 1];
    }

    // ---- init y buffer 0 (CTA 0 of each group) ----
    if (c == 0) {
        for (int i = tid; i < 16 * 512; i += 256) {
            const int row = i >> 9, col = i & 511;
            const float v = y0[(size_t)(g * 16 + row) * Hdim + col];
            const __half hi = __float2half_rn(v);
            g_yhi[(size_t)(g * 16 + row) * 512 + col] = *(const unsigned short*)&hi;
            const __half lo = __float2half_rn(v - __half2float(hi));
            g_ylo[(size_t)(g * 16 + row) * 512 + col] = *(const unsigned short*)&lo;
        }
    }

    unsigned target = 32;
    group_barrier(&g_cnt[g], target); target += 32;

    for (int t = 0; t < Tdim; ++t) {
        // ---- z prefetch (epilogue warps) ----
        float2 zA, zB;
        if (w < 2) {
            zA = *(const float2*)&g_z[((size_t)gbA * Tdim + t) * Hdim + h0];
            zB = *(const float2*)&g_z[((size_t)gbB * Tdim + t) * Hdim + h0];
        }

        // ---- load group's y hi/lo into swizzled smem (L2-only) ----
        {
            const int buf = t & 1;
            const uint4* srcH = (const uint4*)(g_yhi + ((size_t)buf * 64 + g * 16) * 512);
            const uint4* srcL = (const uint4*)(g_ylo + ((size_t)buf * 64 + g * 16) * 512);
#pragma unroll
            for (int i = 0; i < 4; ++i) {
                const int u = tid + i * 256;        // 0..1023
                const int row = u >> 6, ch = u & 63;
                const uint4 vh = __ldcg(srcH + u);
                const uint4 vl = __ldcg(srcL + u);
                const int soff = row * 1024 + ((ch ^ (row & 7)) << 4);
                *(uint4*)(sAhi + soff) = vh;
                *(uint4*)(sAlo + soff) = vl;
            }
        }
        __syncthreads();

        // ---- 3-term split mma over this warp's K half ----
        float dhh[4] = {0, 0, 0, 0}, dlh[4] = {0, 0, 0, 0}, dhl[4] = {0, 0, 0, 0};
#pragma unroll
        for (int kt = 0; kt < 16; ++kt) {
            const int ktg = kh * 16 + kt;
            const uint32_t xoff = (uint32_t)(((ktg * 2 + cq) ^ lr) << 4);
            uint32_t ah0, ah1, ah2, ah3, al0, al1, al2, al3;
            LDSM_X4(ah0, ah1, ah2, ah3, aHiBase + xoff);
            LDSM_X4(al0, al1, al2, al3, aLoBase + xoff);
            MMA16816(dhh, ah0, ah1, ah2, ah3, bh[kt][0], bh[kt][1]);
            MMA16816(dlh, al0, al1, al2, al3, bh[kt][0], bh[kt][1]);
            MMA16816(dhl, ah0, ah1, ah2, ah3, bl[kt][0], bl[kt][1]);
        }
        red4[w * 32 + lane] = make_float4(dhh[0] + dlh[0] + dhl[0],
                                          dhh[1] + dlh[1] + dhl[1],
                                          dhh[2] + dlh[2] + dhl[2],
                                          dhh[3] + dlh[3] + dhl[3]);
        __syncthreads();

        // ---- epilogue (warps 0,1): K-reduce, activations, state, stores ----
        if (w < 2) {
            const float4 iA = red4[w * 32 + lane];
            const float4 iB = red4[(w + 4) * 32 + lane];
            const float4 oA = red4[(w + 2) * 32 + lane];
            const float4 oB = red4[(w + 6) * 32 + lane];
            const float i0 = iA.x + iB.x, i1 = iA.y + iB.y;
            const float i2 = iA.z + iB.z, i3 = iA.w + iB.w;
            const float o0 = oA.x + oB.x, o1 = oA.y + oB.y;
            const float o2 = oA.z + oB.z, o3 = oA.w + oB.w;

            const float ivA0 = tanh_fast(i0 + bi0), ivA1 = tanh_fast(i1 + bi1);
            const float ivB0 = tanh_fast(i2 + bi0), ivB1 = tanh_fast(i3 + bi1);
            const float ovA0 = tanh_fast(o0 + bo0), ovA1 = tanh_fast(o1 + bo1);
            const float ovB0 = tanh_fast(o2 + bo0), ovB1 = tanh_fast(o3 + bo1);

            cA0 += ivA0 * zA.x;  cA1 += ivA1 * zA.y;
            cB0 += ivB0 * zB.x;  cB1 += ivB1 * zB.y;

            const float yA0 = ovA0 * tanh_fast(cA0);
            const float yA1 = ovA1 * tanh_fast(cA1);
            const float yB0 = ovB0 * tanh_fast(cB0);
            const float yB1 = ovB1 * tanh_fast(cB1);

            *(float2*)&out[((size_t)t * Bdim + gbA) * Hdim + h0] = make_float2(yA0, yA1);
            *(float2*)&out[((size_t)t * Bdim + gbB) * Hdim + h0] = make_float2(yB0, yB1);

            // split y -> next buffer
            const int nbuf = (t + 1) & 1;
            const __half hA0 = __float2half_rn(yA0), hA1 = __float2half_rn(yA1);
            const __half hB0 = __float2half_rn(yB0), hB1 = __float2half_rn(yB1);
            *(uint32_t*)&g_yhi[((size_t)nbuf * 64 + gbA) * 512 + h0] = packh2(hA0, hA1);
            *(uint32_t*)&g_yhi[((size_t)nbuf * 64 + gbB) * 512 + h0] = packh2(hB0, hB1);
            *(uint32_t*)&g_ylo[((size_t)nbuf * 64 + gbA) * 512 + h0] =
                packh2(__float2half_rn(yA0 - __half2float(hA0)),
                       __float2half_rn(yA1 - __half2float(hA1)));
            *(uint32_t*)&g_ylo[((size_t)nbuf * 64 + gbB) * 512 + h0] =
                packh2(__float2half_rn(yB0 - __half2float(hB0)),
                       __float2half_rn(yB1 - __half2float(hB1)));

            if (tail && t == Tdim - 1) {
                const size_t base = (size_t)Tdim * Bdim * Hdim;
                out[base + (size_t)gbA * Hdim + h0]     = yA0;
                out[base + (size_t)gbA * Hdim + h0 + 1] = yA1;
                out[base + (size_t)gbB * Hdim + h0]     = yB0;
                out[base + (size_t)gbB * Hdim + h0 + 1] = yB1;
                const size_t cb = base + (size_t)Bdim * Hdim;
                out[cb + (size_t)gbA * Hdim + h0]     = cA0;
                out[cb + (size_t)gbA * Hdim + h0 + 1] = cA1;
                out[cb + (size_t)gbB * Hdim + h0]     = cB0;
                out[cb + (size_t)gbB * Hdim + h0 + 1] = cB1;
            }
        }

        if (t < Tdim - 1) {
            group_barrier(&g_cnt[g], target);
            target += 32;
        }
    }
}

// =====================================================================
extern "C" void kernel_launch(void* const* d_in, const int* in_sizes, int n_in,
                              void* d_out, int out_size) {
    const float* x  = (const float*)d_in[0];
    const float* W  = (const float*)d_in[1];
    const float* R  = (const float*)d_in[2];
    const float* br = (const float*)d_in[3];
    const float* bw = (const float*)d_in[4];
    const float* y0 = (const float*)d_in[5];
    const float* c0 = (const float*)d_in[6];
    float* out = (float*)d_out;

    dim3 g1(Hdim / BN, (Bdim * Tdim) / BM);   // (4, 512)
    phase1<<<g1, 256>>>(x, W, bw);

    const long long full = (long long)Tdim * Bdim * Hdim + 2LL * Bdim * Hdim;
    const int tail = ((long long)out_size >= full) ? 1 : 0;
    phase2<<<128, 256>>>(R, br, y0, c0, out, tail);
}